// round 5
// baseline (speedup 1.0000x reference)
#include <cuda_runtime.h>
#include <cstdint>

#define CIN   80
#define COUT  32
#define BATCH 8
#define HH    160
#define WW    320
#define DD    48
#define HW    (HH*WW)      // 51200
#define RSTR  376          // padded R row stride (floats): 48 zero + 320 + 8
#define CHUNK 16           // channels per staged chunk
#define NCHUNK 5           // 80 / 16
#define BUFBYTES (2*CHUNK*WW*4)   // 40960 B per stage buffer (both images)

// smem byte offsets
#define OFF_SW   0
#define OFF_SB   20480
#define OFF_MBAR 20736     // two 8B mbarriers (full0, full1)
#define OFF_FEAT 20800     // staging (2x40960) then Ls[32][320] | RA[32][376]
#define SMEM_TOTAL (20800 + (32*WW + 32*RSTR)*4)   // 20800 + 89088 = 109888

typedef unsigned long long ull;

__device__ __forceinline__ ull fma2(ull a, ull b, ull c) {
    ull d;
    asm("fma.rn.f32x2 %0, %1, %2, %3;" : "=l"(d) : "l"(a), "l"(b), "l"(c));
    return d;
}
__device__ __forceinline__ ull pack2(float lo, float hi) {
    ull d;
    asm("mov.b64 %0, {%1, %2};" : "=l"(d) : "f"(lo), "f"(hi));
    return d;
}
__device__ __forceinline__ uint32_t s2u(const void* p) {
    uint32_t a;
    asm("{ .reg .u64 t; cvta.to.shared.u64 t, %1; cvt.u32.u64 %0, t; }" : "=r"(a) : "l"(p));
    return a;
}
__device__ __forceinline__ void bulk1d(uint32_t dst, const void* src, uint32_t bytes, uint32_t mbar) {
    asm volatile("cp.async.bulk.shared::cluster.global.mbarrier::complete_tx::bytes [%0], [%1], %2, [%3];"
                 :: "r"(dst), "l"(src), "r"(bytes), "r"(mbar) : "memory");
}
__device__ __forceinline__ void mbar_init(uint32_t mbar, uint32_t cnt) {
    asm volatile("mbarrier.init.shared.b64 [%0], %1;" :: "r"(mbar), "r"(cnt) : "memory");
}
__device__ __forceinline__ void mbar_expect(uint32_t mbar, uint32_t tx) {
    asm volatile("mbarrier.arrive.expect_tx.shared.b64 _, [%0], %1;" :: "r"(mbar), "r"(tx) : "memory");
}
__device__ __forceinline__ void mbar_wait(uint32_t mbar, uint32_t parity) {
    uint32_t done;
    asm volatile("{\n\t.reg .pred p;\n\t"
                 "mbarrier.try_wait.parity.acquire.cta.shared::cta.b64 p, [%1], %2;\n\t"
                 "selp.b32 %0, 1, 0, p;\n\t}" : "=r"(done) : "r"(mbar), "r"(parity) : "memory");
    while (!done) {
        asm volatile("{\n\t.reg .pred p;\n\t"
                     "mbarrier.try_wait.parity.acquire.cta.shared::cta.b64 p, [%1], %2, 0x989680;\n\t"
                     "selp.b32 %0, 1, 0, p;\n\t}" : "=r"(done) : "r"(mbar), "r"(parity) : "memory");
    }
}

// One block per (b,h) row. Phase 1: TMA-staged preconv (relu+bn+1x1, 80->32),
// register tile 4 pixel-pairs x 8 outputs. Phase 2: 48-disparity correlation.
__global__ __launch_bounds__(320, 2) void fused_kernel(
    const float* __restrict__ inL, const float* __restrict__ inR,
    const float* __restrict__ bg,  const float* __restrict__ bb,
    const float* __restrict__ bm,  const float* __restrict__ bv,
    const float* __restrict__ cw,  const float* __restrict__ cb,
    float* __restrict__ out)
{
    extern __shared__ char smraw[];
    ull*   sW   = (ull*)(smraw + OFF_SW);     // [80][32] splatted folded weights
    ull*   sB   = (ull*)(smraw + OFF_SB);     // [32]
    float* feat = (float*)(smraw + OFF_FEAT); // staging, later Ls|RA
    float* Ls   = feat;                       // [32][320]
    float* RA   = feat + 32*WW;               // [32][376]
    const uint32_t smbase = s2u(smraw);
    const uint32_t mb0 = smbase + OFF_MBAR;

    const int tid = threadIdx.x;
    const int bh  = blockIdx.x;
    const int h   = bh % HH, b = bh / HH;
    const long base_in = (long)b * CIN * HW + (long)h * WW;

    // ---- Phase 0: mbarriers + weight folding ----
    if (tid == 0) { mbar_init(mb0, 1); mbar_init(mb0 + 8, 1); }
    __syncthreads();

    if (tid == 0) {
        // issue chunks 0 and 1
        #pragma unroll
        for (int k = 0; k < 2; k++) {
            uint32_t mbar = mb0 + (k & 1) * 8;
            mbar_expect(mbar, BUFBYTES);
            uint32_t dst = smbase + OFF_FEAT + (k & 1) * BUFBYTES;
            const float* srcL = inL + base_in + (long)(k * CHUNK) * HW;
            const float* srcR = inR + base_in + (long)(k * CHUNK) * HW;
            for (int cc = 0; cc < CHUNK; cc++) {
                bulk1d(dst + cc * 1280,                srcL + (long)cc * HW, 1280, mbar);
                bulk1d(dst + CHUNK * 1280 + cc * 1280, srcR + (long)cc * HW, 1280, mbar);
            }
        }
    }

    for (int idx = tid; idx < CIN * COUT; idx += 320) {
        int c = idx >> 5, o = idx & 31;
        float sc = bg[c] * rsqrtf(bv[c] + 1e-5f);
        float wv = cw[o * CIN + c] * sc;
        sW[idx] = pack2(wv, wv);
    }
    if (tid < COUT) {
        float s = cb[tid];
        for (int c = 0; c < CIN; c++) {
            float sc = bg[c] * rsqrtf(bv[c] + 1e-5f);
            s += cw[tid * CIN + c] * (bb[c] - bm[c] * sc);
        }
        sB[tid] = pack2(s, s);
    }
    __syncthreads();   // <<< FIX: sW/sB must be complete before any thread reads them

    // ---- Phase 1: preconv from staged smem ----
    const int pg = tid % 80;   // pair-group (lanes mostly consecutive)
    const int og = tid / 80;   // output group 0..3

    ull acc[32];
    #pragma unroll
    for (int i = 0; i < 32; i++) acc[i] = sB[og * 8 + (i & 7)];

    for (int k = 0; k < NCHUNK; k++) {
        const int s = k & 1;
        mbar_wait(mb0 + s * 8, (k >> 1) & 1);
        const float* bufL = feat + s * (BUFBYTES / 4);
        const float* bufR = bufL + CHUNK * WW;

        #pragma unroll 2
        for (int cc = 0; cc < CHUNK; cc++) {
            const float* pL = bufL + cc * WW + 2 * pg;
            const float* pR = bufR + cc * WW + 2 * pg;
            float2 a0 = *(const float2*)(pL);
            float2 a1 = *(const float2*)(pL + 160);
            float2 a2 = *(const float2*)(pR);
            float2 a3 = *(const float2*)(pR + 160);
            ull x0 = pack2(fmaxf(a0.x, 0.f), fmaxf(a0.y, 0.f));
            ull x1 = pack2(fmaxf(a1.x, 0.f), fmaxf(a1.y, 0.f));
            ull x2 = pack2(fmaxf(a2.x, 0.f), fmaxf(a2.y, 0.f));
            ull x3 = pack2(fmaxf(a3.x, 0.f), fmaxf(a3.y, 0.f));
            const ull* wr = &sW[(k * CHUNK + cc) * 32 + og * 8];
            #pragma unroll
            for (int oo = 0; oo < 8; oo++) {
                ull w = wr[oo];           // broadcast LDS.64
                acc[oo]      = fma2(x0, w, acc[oo]);
                acc[8 + oo]  = fma2(x1, w, acc[8 + oo]);
                acc[16 + oo] = fma2(x2, w, acc[16 + oo]);
                acc[24 + oo] = fma2(x3, w, acc[24 + oo]);
            }
        }
        __syncthreads();   // all threads done reading buffer s
        if (tid == 0 && k + 2 < NCHUNK) {
            int kn = k + 2;
            uint32_t mbar = mb0 + s * 8;
            mbar_expect(mbar, BUFBYTES);
            uint32_t dst = smbase + OFF_FEAT + s * BUFBYTES;
            const float* srcL = inL + base_in + (long)(kn * CHUNK) * HW;
            const float* srcR = inR + base_in + (long)(kn * CHUNK) * HW;
            for (int cc = 0; cc < CHUNK; cc++) {
                bulk1d(dst + cc * 1280,                srcL + (long)cc * HW, 1280, mbar);
                bulk1d(dst + CHUNK * 1280 + cc * 1280, srcR + (long)cc * HW, 1280, mbar);
            }
        }
    }

    // staging fully consumed; overwrite with Ls / RA
    // zero RA pads: per row o, cols [0,48) and [368,376)
    for (int idx = tid; idx < 32 * 56; idx += 320) {
        int o = idx / 56, j = idx % 56;
        RA[o * RSTR + (j < 48 ? j : 320 + j)] = 0.f;
    }
    #pragma unroll
    for (int kk = 0; kk < 4; kk++) {
        int w0 = 2 * pg + (kk & 1) * 160;
        #pragma unroll
        for (int oo = 0; oo < 8; oo++) {
            int o = og * 8 + oo;
            if (kk < 2) *(ull*)&Ls[o * WW   + w0]      = acc[kk * 8 + oo];
            else        *(ull*)&RA[o * RSTR + w0 + 48] = acc[kk * 8 + oo];
        }
    }
    __syncthreads();

    // ---- Phase 2: correlation. 640 tiles (160 w-pairs x 4 d-groups) ----
    float* outp = out + ((long)b * DD * HH + h) * WW;
    for (int T = tid; T < 640; T += 320) {
        const int wp = T % 160;
        const int ig = T / 160;
        const int i0 = ig * 12;
        const int w0 = 2 * wp;
        const int rbase = w0 + 36 - i0;

        ull acc2[12];
        #pragma unroll
        for (int d = 0; d < 12; d++) acc2[d] = 0ULL;

        for (int c = 0; c < 32; c++) {
            ull Lp = *(const ull*)&Ls[c * WW + w0];
            const float* rr = &RA[c * RSTR + rbase];
            ull V[7];
            #pragma unroll
            for (int j = 0; j < 7; j++) V[j] = *(const ull*)&rr[2 * j];
            #pragma unroll
            for (int dp = 0; dp < 12; dp++) {
                ull v;
                if ((dp & 1) == 0) {
                    v = V[6 - dp / 2];
                } else {
                    float2 va = *(float2*)&V[(11 - dp) / 2];
                    float2 vb = *(float2*)&V[(13 - dp) / 2];
                    v = pack2(va.y, vb.x);
                }
                acc2[dp] = fma2(Lp, v, acc2[dp]);
            }
        }
        #pragma unroll
        for (int dp = 0; dp < 12; dp++) {
            float2 v = *(float2*)&acc2[dp];
            v.x *= 0.03125f;
            v.y *= 0.03125f;
            *(float2*)&outp[(long)(i0 + dp) * HW + w0] = v;
        }
    }
}

// ---------------------------------------------------------------------------
extern "C" void kernel_launch(void* const* d_in, const int* in_sizes, int n_in,
                              void* d_out, int out_size)
{
    const float* fL = (const float*)d_in[0];
    const float* fR = (const float*)d_in[1];
    const float* bg = (const float*)d_in[2];
    const float* bb = (const float*)d_in[3];
    const float* bm = (const float*)d_in[4];
    const float* bv = (const float*)d_in[5];
    const float* cw = (const float*)d_in[6];
    const float* cb = (const float*)d_in[7];
    float* out = (float*)d_out;

    cudaFuncSetAttribute(fused_kernel, cudaFuncAttributeMaxDynamicSharedMemorySize, SMEM_TOTAL);
    fused_kernel<<<BATCH*HH, 320, SMEM_TOTAL>>>(fL, fR, bg, bb, bm, bv, cw, cb, out);
}

// round 7
// speedup vs baseline: 1.6388x; 1.6388x over previous
#include <cuda_runtime.h>
#include <cstdint>

#define CIN   80
#define COUT  32
#define BATCH 8
#define HH    160
#define WW    320
#define DD    48
#define HW    (HH*WW)      // 51200
#define RSTR  376          // padded R row stride (floats): 48 zero + 320 + 8 (16B-mult)
#define CHUNK 16
#define NCHUNK 5
#define BUFBYTES (2*CHUNK*WW*4)   // 40960 B per stage buffer

#define OFF_SW   0
#define OFF_SB   20480
#define OFF_MBAR 20736
#define OFF_FEAT 20800
#define SMEM_TOTAL (20800 + (32*WW + 32*RSTR)*4)   // 109888

typedef unsigned long long ull;

__device__ __forceinline__ ull fma2(ull a, ull b, ull c) {
    ull d;
    asm("fma.rn.f32x2 %0, %1, %2, %3;" : "=l"(d) : "l"(a), "l"(b), "l"(c));
    return d;
}
__device__ __forceinline__ ull mul2(ull a, ull b) {
    ull d;
    asm("mul.rn.f32x2 %0, %1, %2;" : "=l"(d) : "l"(a), "l"(b));
    return d;
}
__device__ __forceinline__ ull pack2(float lo, float hi) {
    ull d;
    asm("mov.b64 %0, {%1, %2};" : "=l"(d) : "f"(lo), "f"(hi));
    return d;
}
__device__ __forceinline__ uint32_t s2u(const void* p) {
    uint32_t a;
    asm("{ .reg .u64 t; cvta.to.shared.u64 t, %1; cvt.u32.u64 %0, t; }" : "=r"(a) : "l"(p));
    return a;
}
__device__ __forceinline__ void bulk1d(uint32_t dst, const void* src, uint32_t bytes, uint32_t mbar) {
    asm volatile("cp.async.bulk.shared::cluster.global.mbarrier::complete_tx::bytes [%0], [%1], %2, [%3];"
                 :: "r"(dst), "l"(src), "r"(bytes), "r"(mbar) : "memory");
}
__device__ __forceinline__ void mbar_init(uint32_t mbar, uint32_t cnt) {
    asm volatile("mbarrier.init.shared.b64 [%0], %1;" :: "r"(mbar), "r"(cnt) : "memory");
}
__device__ __forceinline__ void mbar_expect(uint32_t mbar, uint32_t tx) {
    asm volatile("mbarrier.arrive.expect_tx.shared.b64 _, [%0], %1;" :: "r"(mbar), "r"(tx) : "memory");
}
__device__ __forceinline__ void mbar_wait(uint32_t mbar, uint32_t parity) {
    uint32_t done;
    asm volatile("{\n\t.reg .pred p;\n\t"
                 "mbarrier.try_wait.parity.acquire.cta.shared::cta.b64 p, [%1], %2;\n\t"
                 "selp.b32 %0, 1, 0, p;\n\t}" : "=r"(done) : "r"(mbar), "r"(parity) : "memory");
    while (!done) {
        asm volatile("{\n\t.reg .pred p;\n\t"
                     "mbarrier.try_wait.parity.acquire.cta.shared::cta.b64 p, [%1], %2, 0x989680;\n\t"
                     "selp.b32 %0, 1, 0, p;\n\t}" : "=r"(done) : "r"(mbar), "r"(parity) : "memory");
    }
}

// One block per (b,h) row.
__global__ __launch_bounds__(320, 2) void fused_kernel(
    const float* __restrict__ inL, const float* __restrict__ inR,
    const float* __restrict__ bg,  const float* __restrict__ bb,
    const float* __restrict__ bm,  const float* __restrict__ bv,
    const float* __restrict__ cw,  const float* __restrict__ cb,
    float* __restrict__ out)
{
    extern __shared__ char smraw[];
    ull*   sW   = (ull*)(smraw + OFF_SW);     // [80][32] splatted folded weights
    ull*   sB   = (ull*)(smraw + OFF_SB);     // [32]
    float* feat = (float*)(smraw + OFF_FEAT); // staging, later Ls|RA
    float* Ls   = feat;                       // [32][320]  (scaled by 1/32)
    float* RA   = feat + 32*WW;               // [32][376], RA[o][j] = featR[o][j-48]
    const uint32_t smbase = s2u(smraw);
    const uint32_t mb0 = smbase + OFF_MBAR;

    const int tid = threadIdx.x;
    const int bh  = blockIdx.x;
    const int h   = bh % HH, b = bh / HH;
    const long base_in = (long)b * CIN * HW + (long)h * WW;

    // ---- Phase 0: mbarriers + first two TMA chunks + weight folding ----
    if (tid == 0) { mbar_init(mb0, 1); mbar_init(mb0 + 8, 1); }
    __syncthreads();

    if (tid == 0) {
        #pragma unroll
        for (int k = 0; k < 2; k++) {
            uint32_t mbar = mb0 + k * 8;
            mbar_expect(mbar, BUFBYTES);
            uint32_t dst = smbase + OFF_FEAT + k * BUFBYTES;
            const float* srcL = inL + base_in + (long)(k * CHUNK) * HW;
            const float* srcR = inR + base_in + (long)(k * CHUNK) * HW;
            for (int cc = 0; cc < CHUNK; cc++) {
                bulk1d(dst + cc * 1280,                srcL + (long)cc * HW, 1280, mbar);
                bulk1d(dst + CHUNK * 1280 + cc * 1280, srcR + (long)cc * HW, 1280, mbar);
            }
        }
    }

    for (int idx = tid; idx < CIN * COUT; idx += 320) {
        int c = idx >> 5, o = idx & 31;
        float sc = bg[c] * rsqrtf(bv[c] + 1e-5f);
        float wv = cw[o * CIN + c] * sc;
        sW[idx] = pack2(wv, wv);
    }
    if (tid < COUT) {
        float s = cb[tid];
        for (int c = 0; c < CIN; c++) {
            float sc = bg[c] * rsqrtf(bv[c] + 1e-5f);
            s += cw[tid * CIN + c] * (bb[c] - bm[c] * sc);
        }
        sB[tid] = pack2(s, s);
    }
    __syncthreads();

    // ---- Phase 1: preconv. Thread = (dg, og): one float4 (2 pairs) x 16 outputs.
    const int dg  = tid % 160;
    const int og  = tid / 160;          // 0/1 -> outputs og*16..og*16+15
    const int img = dg / 80;            // 0 = L, 1 = R
    const int w0p = 4 * (dg % 80);      // float4 position in row

    ull accA[16], accB[16];             // pair0 / pair1 accumulators
    #pragma unroll
    for (int oo = 0; oo < 16; oo++) { accA[oo] = sB[og * 16 + oo]; accB[oo] = accA[oo]; }

    for (int k = 0; k < NCHUNK; k++) {
        const int s = k & 1;
        mbar_wait(mb0 + s * 8, (k >> 1) & 1);
        const float* bufD = feat + s * (BUFBYTES / 4) + img * (CHUNK * WW) + w0p;

        for (int cc = 0; cc < CHUNK; cc++) {
            float4 xv = *(const float4*)(bufD + cc * WW);
            ull x01 = pack2(fmaxf(xv.x, 0.f), fmaxf(xv.y, 0.f));
            ull x23 = pack2(fmaxf(xv.z, 0.f), fmaxf(xv.w, 0.f));
            const ulonglong2* wr = (const ulonglong2*)&sW[(k * CHUNK + cc) * 32 + og * 16];
            #pragma unroll
            for (int j = 0; j < 8; j++) {
                ulonglong2 W2 = wr[j];          // broadcast LDS.128 (2 outputs)
                accA[2*j]   = fma2(x01, W2.x, accA[2*j]);
                accB[2*j]   = fma2(x23, W2.x, accB[2*j]);
                accA[2*j+1] = fma2(x01, W2.y, accA[2*j+1]);
                accB[2*j+1] = fma2(x23, W2.y, accB[2*j+1]);
            }
        }
        __syncthreads();   // buffer s fully consumed by all threads
        if (tid == 0 && k + 2 < NCHUNK) {
            int kn = k + 2;
            uint32_t mbar = mb0 + s * 8;
            mbar_expect(mbar, BUFBYTES);
            uint32_t dst = smbase + OFF_FEAT + s * BUFBYTES;
            const float* srcL = inL + base_in + (long)(kn * CHUNK) * HW;
            const float* srcR = inR + base_in + (long)(kn * CHUNK) * HW;
            for (int cc = 0; cc < CHUNK; cc++) {
                bulk1d(dst + cc * 1280,                srcL + (long)cc * HW, 1280, mbar);
                bulk1d(dst + CHUNK * 1280 + cc * 1280, srcR + (long)cc * HW, 1280, mbar);
            }
        }
    }

    // zero RA pads: cols [0,48) and [368,376)
    for (int idx = tid; idx < 32 * 56; idx += 320) {
        int o = idx / 56, j = idx % 56;
        RA[o * RSTR + (j < 48 ? j : 320 + j)] = 0.f;
    }
    // fold 1/32 into the L features at store time
    if (img == 0) {
        const ull inv2 = pack2(0.03125f, 0.03125f);
        #pragma unroll
        for (int oo = 0; oo < 16; oo++) { accA[oo] = mul2(accA[oo], inv2); accB[oo] = mul2(accB[oo], inv2); }
        #pragma unroll
        for (int oo = 0; oo < 16; oo++) {
            int o = og * 16 + oo;
            ulonglong2 v; v.x = accA[oo]; v.y = accB[oo];
            *(ulonglong2*)&Ls[o * WW + w0p] = v;            // STS.128
        }
    } else {
        #pragma unroll
        for (int oo = 0; oo < 16; oo++) {
            int o = og * 16 + oo;
            ulonglong2 v; v.x = accA[oo]; v.y = accB[oo];
            *(ulonglong2*)&RA[o * RSTR + w0p + 48] = v;     // STS.128
        }
    }
    __syncthreads();

    // ---- Phase 2: correlation. Thread = (wq, ig): 2 pairs (4 w) x 12 disparities.
    const int wq = tid % 80, ig = tid / 80;
    const int W0 = 4 * wq;              // 16B aligned
    const int i0 = 12 * ig;             // multiple of 4 -> V window 16B aligned

    ull aP[12], aQ[12];
    #pragma unroll
    for (int d = 0; d < 12; d++) { aP[d] = 0ULL; aQ[d] = 0ULL; }

    for (int c = 0; c < 32; c++) {
        ulonglong2 Lp = *(const ulonglong2*)&Ls[c * WW + W0];      // pairs (W0,W0+1),(W0+2,W0+3)
        const float* rr = &RA[c * RSTR + W0 + 36 - i0];            // 16B aligned
        ull V[8];
        #pragma unroll
        for (int m = 0; m < 4; m++) {
            ulonglong2 t = *(const ulonglong2*)&rr[4 * m];         // LDS.128
            V[2*m] = t.x; V[2*m+1] = t.y;
        }
        #pragma unroll
        for (int dd = 0; dd < 12; dd++) {
            ull v0, v1;
            if ((dd & 1) == 0) {
                v0 = V[(12 - dd) / 2];
                v1 = V[(14 - dd) / 2];
            } else {
                const float2* f11 = (const float2*)&V[(11 - dd) / 2];
                const float2* f13 = (const float2*)&V[(13 - dd) / 2];
                const float2* f15 = (const float2*)&V[(15 - dd) / 2];
                v0 = pack2(f11->y, f13->x);
                v1 = pack2(f13->y, f15->x);
            }
            aP[dd] = fma2(Lp.x, v0, aP[dd]);
            aQ[dd] = fma2(Lp.y, v1, aQ[dd]);
        }
    }

    float* outp = out + ((long)b * DD * HH + h) * WW;
    #pragma unroll
    for (int dd = 0; dd < 12; dd++) {
        float2 p = *(float2*)&aP[dd];
        float2 q = *(float2*)&aQ[dd];
        float4 v; v.x = p.x; v.y = p.y; v.z = q.x; v.w = q.y;     // already scaled via Ls
        *(float4*)&outp[(long)(i0 + dd) * HW + W0] = v;            // STG.128
    }
}

// ---------------------------------------------------------------------------
extern "C" void kernel_launch(void* const* d_in, const int* in_sizes, int n_in,
                              void* d_out, int out_size)
{
    const float* fL = (const float*)d_in[0];
    const float* fR = (const float*)d_in[1];
    const float* bg = (const float*)d_in[2];
    const float* bb = (const float*)d_in[3];
    const float* bm = (const float*)d_in[4];
    const float* bv = (const float*)d_in[5];
    const float* cw = (const float*)d_in[6];
    const float* cb = (const float*)d_in[7];
    float* out = (float*)d_out;

    cudaFuncSetAttribute(fused_kernel, cudaFuncAttributeMaxDynamicSharedMemorySize, SMEM_TOTAL);
    fused_kernel<<<BATCH*HH, 320, SMEM_TOTAL>>>(fL, fR, bg, bb, bm, bv, cw, cb, out);
}